// round 3
// baseline (speedup 1.0000x reference)
#include <cuda_runtime.h>
#include <cstdint>

// =====================================================================
// SESNetwork closed-form rewrite.
//
// Key insight: activations are independent of the plastic weights, and
// Hebbian+homeostasis over binary masks reduces to
//   w_ij = lambda * sum_{t : post_i(t) & pre_j(t)} S_i(t),
//   S_i(t) = prod_{s>=t} scale_i(s),
// where scale_i depends only on row i's 50-bit post mask (nnz_pre const).
// So each output matrix is written exactly once.
// =====================================================================

#define TF_PARTITIONABLE 1   // JAX >= 0.5.0 default (threefry_partitionable)

#define SEN    2048
#define MTL_D  1024
#define MTL_S  3072
#define MTL    4096
#define CTX    4096
#define NSTEP  50

#define K_SEN   102   // int(2048*0.05)
#define K_DEN   51    // int(1024*0.05)
#define K_SPA   38    // int(768*0.05)
#define NNZ_MTL 203   // 51 + 4*38
#define NNZ_DEN 51
#define NNZ_CTX 204   // 4*51

#define OFF_WMTL   0LL
#define OFF_WDENSE 16777216LL
#define OFF_WCTX   17825792LL
#define OFF_CTXV   34603008LL

// ------------------------- scratch (static device) -------------------------
__device__ unsigned long long g_mtlmask[MTL];   // bit t set if mtl neuron active at step t
__device__ unsigned long long g_ctxmask[CTX];
__device__ unsigned short     g_sen_idx[NSTEP][128];   // 102 used
__device__ unsigned short     g_mtl_idx[NSTEP][256];   // 203 used
__device__ float              g_hat_dense[NSTEP][MTL_D];
__device__ float              g_hat_ctx[NSTEP][CTX];
__device__ float              g_S_mtl[MTL][NSTEP];
__device__ float              g_S_dense[MTL_D][NSTEP];
__device__ float              g_S_ctx[CTX][NSTEP];

// ------------------------- threefry2x32 -------------------------
__device__ __forceinline__ uint2 tf2x32(uint32_t k0, uint32_t k1,
                                        uint32_t x0, uint32_t x1) {
  uint32_t k2 = k0 ^ k1 ^ 0x1BD11BDAu;
#define TFR(r) { x0 += x1; x1 = (x1 << (r)) | (x1 >> (32 - (r))); x1 ^= x0; }
  x0 += k0; x1 += k1;
  TFR(13) TFR(15) TFR(26) TFR(6)
  x0 += k1; x1 += k2 + 1u;
  TFR(17) TFR(29) TFR(16) TFR(24)
  x0 += k2; x1 += k0 + 2u;
  TFR(13) TFR(15) TFR(26) TFR(6)
  x0 += k0; x1 += k1 + 3u;
  TFR(17) TFR(29) TFR(16) TFR(24)
  x0 += k1; x1 += k2 + 4u;
  TFR(13) TFR(15) TFR(26) TFR(6)
  x0 += k2; x1 += k0 + 5u;
#undef TFR
  return make_uint2(x0, x1);
}

// fold_in(key(42), t) : cipher([0,42], [0,t])
__device__ __forceinline__ uint2 fold_key(int t) {
  return tf2x32(0u, 42u, 0u, (uint32_t)t);
}

// split(fkey, 5)[which]
__device__ __forceinline__ uint2 skey(uint2 f, int which) {
#if TF_PARTITIONABLE
  return tf2x32(f.x, f.y, 0u, (uint32_t)which);
#else
  // original split: flat = concat(out0[0..4], out1[0..4]) with pairs (i, i+5)
  uint32_t r[2];
  for (int h = 0; h < 2; h++) {
    int idx = 2 * which + h;
    if (idx < 5) { uint2 o = tf2x32(f.x, f.y, (uint32_t)idx, (uint32_t)(idx + 5)); r[h] = o.x; }
    else         { uint2 o = tf2x32(f.x, f.y, (uint32_t)(idx - 5), (uint32_t)idx); r[h] = o.y; }
  }
  return make_uint2(r[0], r[1]);
#endif
}

// XLA f32 ErfInv (Giles polynomial)
__device__ __forceinline__ float erfinv_xla(float x) {
  float xx = x * x;
  float w = -log1pf(-xx);
  float p;
  if (w < 5.0f) {
    w -= 2.5f;
    p = 2.81022636e-08f;
    p = fmaf(p, w, 3.43273939e-07f);
    p = fmaf(p, w, -3.5233877e-06f);
    p = fmaf(p, w, -4.39150654e-06f);
    p = fmaf(p, w, 0.00021858087f);
    p = fmaf(p, w, -0.00125372503f);
    p = fmaf(p, w, -0.00417768164f);
    p = fmaf(p, w, 0.246640727f);
    p = fmaf(p, w, 1.50140941f);
  } else {
    w = sqrtf(w) - 3.0f;
    p = -0.000200214257f;
    p = fmaf(p, w, 0.000100950558f);
    p = fmaf(p, w, 0.00134934322f);
    p = fmaf(p, w, -0.00367342844f);
    p = fmaf(p, w, 0.00573950773f);
    p = fmaf(p, w, -0.0076224613f);
    p = fmaf(p, w, 0.00943887047f);
    p = fmaf(p, w, 1.00167406f);
    p = fmaf(p, w, 2.83297682f);
  }
  return p * x;
}

// jax.random.normal(key, (N,))[j], float32
__device__ __forceinline__ float jnormal(uint2 key, uint32_t j, uint32_t N) {
  uint32_t bits;
#if TF_PARTITIONABLE
  uint2 o = tf2x32(key.x, key.y, 0u, j);   // hi=0 for N < 2^32
  bits = o.x ^ o.y;
#else
  uint32_t h = N / 2;  // all our N are even
  if (j < h) { uint2 o = tf2x32(key.x, key.y, j, j + h);     bits = o.x; }
  else       { uint2 o = tf2x32(key.x, key.y, j - h, j);     bits = o.y; }
#endif
  float f = __uint_as_float((bits >> 9) | 0x3f800000u) - 1.0f;
  const float LO = -0.99999994039535522461f;         // nextafter(-1, 0)
  float u = fmaxf(LO, fmaf(f, 2.0f, LO));            // (1 - LO) rounds to 2.0f
  return 1.4142135381698608f * erfinv_xla(u);        // float32(sqrt(2))
}

// composite sort key: descending float, then ascending index on ties
__device__ __forceinline__ unsigned long long ckey(float v, uint32_t idx) {
  uint32_t u = __float_as_uint(v);
  u = (u & 0x80000000u) ? ~u : (u | 0x80000000u);
  return ((unsigned long long)u << 32) | (uint32_t)(~idx);
}

// block max/min over all threads (all threads must call)
__device__ void block_maxmin(float x, float n, float* s_red, float& omx, float& omn) {
  int lane = threadIdx.x & 31, w = threadIdx.x >> 5;
  int nw = (int)(blockDim.x >> 5);
  for (int o = 16; o; o >>= 1) {
    x = fmaxf(x, __shfl_xor_sync(0xffffffffu, x, o));
    n = fminf(n, __shfl_xor_sync(0xffffffffu, n, o));
  }
  if (lane == 0) { s_red[w] = x; s_red[32 + w] = n; }
  __syncthreads();
  if (w == 0) {
    x = (lane < nw) ? s_red[lane]      : -3.402823466e38f;
    n = (lane < nw) ? s_red[32 + lane] :  3.402823466e38f;
    for (int o = 16; o; o >>= 1) {
      x = fmaxf(x, __shfl_xor_sync(0xffffffffu, x, o));
      n = fminf(n, __shfl_xor_sync(0xffffffffu, n, o));
    }
    if (lane == 0) { s_red[0] = x; s_red[32] = n; }
  }
  __syncthreads();
  omx = s_red[0]; omn = s_red[32];
  __syncthreads();  // protect scratch reuse by a later call
}

// ------------------------- kernels -------------------------

__global__ void k_zero() {
  int i = blockIdx.x * blockDim.x + threadIdx.x;
  if (i < MTL) { g_mtlmask[i] = 0ull; g_ctxmask[i] = 0ull; }
}

// sen activation: one block per step, 1024 threads
__global__ void k_sen(const float* __restrict__ input) {
  __shared__ unsigned long long sk[SEN];
  __shared__ float s_red[64];
  __shared__ int s_cnt;
  int t = blockIdx.x, tid = threadIdx.x;
  if (tid == 0) s_cnt = 0;
  uint2 f = fold_key(t);
  uint2 kn = skey(f, 0);
  float v0 = input[t * SEN + tid];
  float v1 = input[t * SEN + tid + 1024];
  float mx, mn;
  block_maxmin(fmaxf(v0, v1), fminf(v0, v1), s_red, mx, mn);
  float amp = ((1e-10f + mx) - mn) / 100.0f;
  sk[tid]        = ckey(v0 + amp * jnormal(kn, (uint32_t)tid, SEN), (uint32_t)tid);
  sk[tid + 1024] = ckey(v1 + amp * jnormal(kn, (uint32_t)(tid + 1024), SEN), (uint32_t)(tid + 1024));
  __syncthreads();
  unsigned long long a = sk[tid], b = sk[tid + 1024];
  int c0 = 0, c1 = 0;
  for (int m = 0; m < SEN; m++) {
    unsigned long long km = sk[m];
    c0 += (km > a); c1 += (km > b);
  }
  if (c0 < K_SEN) g_sen_idx[t][atomicAdd(&s_cnt, 1)] = (unsigned short)tid;
  if (c1 < K_SEN) g_sen_idx[t][atomicAdd(&s_cnt, 1)] = (unsigned short)(tid + 1024);
}

// dense matvec: one block per dense row; all 50 steps gather from the smem row
__global__ void k_dense_mv(const float* __restrict__ Wds) {
  __shared__ float row[SEN];                 // 8 KB
  __shared__ unsigned short idx[NSTEP * 128]; // 12.8 KB
  int r = blockIdx.x, tid = threadIdx.x;     // 256 threads
  for (int i = tid; i < SEN; i += 256) row[i] = Wds[(long long)r * SEN + i];
  const unsigned short* src = &g_sen_idx[0][0];
  for (int i = tid; i < NSTEP * 128; i += 256) idx[i] = src[i];
  __syncthreads();
  int w = tid >> 5, l = tid & 31;            // 8 warps
  for (int t = w; t < NSTEP; t += 8) {
    double acc = 0.0;
    for (int m = l; m < K_SEN; m += 32) acc += (double)row[idx[t * 128 + m]];
    for (int o = 16; o; o >>= 1) acc += __shfl_xor_sync(0xffffffffu, acc, o);
    if (l == 0) g_hat_dense[t][r] = (float)acc;
  }
}

// mtl activation: dense top-k (1024, 1 sub) + sparse hat/top-k (3072, 4 subs)
__global__ void k_mtl_act() {
  __shared__ unsigned long long kd[MTL_D];   // 8 KB
  __shared__ unsigned long long ksp[MTL_S];  // 24 KB
  __shared__ float s_red[64];
  __shared__ int s_cnt;
  int t = blockIdx.x, tid = threadIdx.x;     // 1024 threads
  if (tid == 0) s_cnt = 0;
  uint2 f = fold_key(t);
  uint2 K1 = skey(f, 1), K2 = skey(f, 2), K3 = skey(f, 3);

  float vd  = g_hat_dense[t][tid];
  float vs0 = jnormal(K2, (uint32_t)tid,          MTL_S);
  float vs1 = jnormal(K2, (uint32_t)(tid + 1024), MTL_S);
  float vs2 = jnormal(K2, (uint32_t)(tid + 2048), MTL_S);

  float mx, mn;
  block_maxmin(vd, vd, s_red, mx, mn);
  float amp_d = ((1e-10f + mx) - mn) / 100.0f;
  block_maxmin(fmaxf(vs0, fmaxf(vs1, vs2)), fminf(vs0, fminf(vs1, vs2)), s_red, mx, mn);
  float amp_s = ((1e-10f + mx) - mn) / 100.0f;

  kd[tid] = ckey(vd + amp_d * jnormal(K1, (uint32_t)tid, MTL_D), (uint32_t)tid);
  ksp[tid]        = ckey(vs0 + amp_s * jnormal(K3, (uint32_t)tid,          MTL_S), (uint32_t)tid);
  ksp[tid + 1024] = ckey(vs1 + amp_s * jnormal(K3, (uint32_t)(tid + 1024), MTL_S), (uint32_t)(tid + 1024));
  ksp[tid + 2048] = ckey(vs2 + amp_s * jnormal(K3, (uint32_t)(tid + 2048), MTL_S), (uint32_t)(tid + 2048));
  __syncthreads();

  {
    unsigned long long a = kd[tid];
    int c = 0;
    for (int m = 0; m < MTL_D; m++) c += (kd[m] > a);
    if (c < K_DEN) {
      g_mtl_idx[t][atomicAdd(&s_cnt, 1)] = (unsigned short)tid;
      atomicOr(&g_mtlmask[tid], 1ull << t);
    }
  }
  for (int e = 0; e < 3; e++) {
    int j = tid + e * 1024;
    int base = (j / 768) * 768;
    unsigned long long a = ksp[j];
    int c = 0;
    for (int m = 0; m < 768; m++) c += (ksp[base + m] > a);
    if (c < K_SPA) {
      g_mtl_idx[t][atomicAdd(&s_cnt, 1)] = (unsigned short)(MTL_D + j);
      atomicOr(&g_mtlmask[MTL_D + j], 1ull << t);
    }
  }
}

// ctx matvec: one block per ctx row; all 50 steps gather from smem row
__global__ void k_ctx_mv(const float* __restrict__ Wcm) {
  __shared__ float row[MTL];                  // 16 KB
  __shared__ unsigned short idx[NSTEP * 256]; // 25.6 KB
  int r = blockIdx.x, tid = threadIdx.x;      // 512 threads
  for (int i = tid; i < MTL; i += 512) row[i] = Wcm[(long long)r * MTL + i];
  const unsigned short* src = &g_mtl_idx[0][0];
  for (int i = tid; i < NSTEP * 256; i += 512) idx[i] = src[i];
  __syncthreads();
  int w = tid >> 5, l = tid & 31;             // 16 warps
  for (int t = w; t < NSTEP; t += 16) {
    double acc = 0.0;
    for (int m = l; m < NNZ_MTL; m += 32) acc += (double)row[idx[t * 256 + m]];
    for (int o = 16; o; o >>= 1) acc += __shfl_xor_sync(0xffffffffu, acc, o);
    if (l == 0) g_hat_ctx[t][r] = (float)acc;
  }
}

// ctx activation (4096, 4 subs); emits final ctx vector at t==49
__global__ void k_ctx_act(float* __restrict__ out_ctx) {
  __shared__ unsigned long long kc[CTX];      // 32 KB
  __shared__ float s_red[64];
  int t = blockIdx.x, tid = threadIdx.x;      // 1024 threads
  uint2 f = fold_key(t);
  uint2 K4 = skey(f, 4);
  float v[4];
  float lmx = -3.402823466e38f, lmn = 3.402823466e38f;
  for (int e = 0; e < 4; e++) {
    v[e] = g_hat_ctx[t][tid + e * 1024];
    lmx = fmaxf(lmx, v[e]); lmn = fminf(lmn, v[e]);
  }
  float mx, mn;
  block_maxmin(lmx, lmn, s_red, mx, mn);
  float amp = ((1e-10f + mx) - mn) / 100.0f;
  for (int e = 0; e < 4; e++) {
    int j = tid + e * 1024;
    kc[j] = ckey(v[e] + amp * jnormal(K4, (uint32_t)j, CTX), (uint32_t)j);
  }
  __syncthreads();
  for (int e = 0; e < 4; e++) {
    int j = tid + e * 1024;
    int base = j & ~1023;
    unsigned long long a = kc[j];
    int c = 0;
    for (int m = 0; m < 1024; m++) c += (kc[base + m] > a);
    bool sel = (c < K_DEN);  // k = 51
    if (sel) atomicOr(&g_ctxmask[j], 1ull << t);
    if (t == NSTEP - 1) out_ctx[j] = sel ? 1.0f : 0.0f;
  }
}

// per-row homeostasis scale suffix products
__global__ void k_scales() {
  int id = blockIdx.x * blockDim.x + threadIdx.x;
  if (id >= MTL + MTL_D + CTX) return;
  unsigned long long mask; int nnz; float* S;
  if (id < MTL)               { mask = g_mtlmask[id];        nnz = NNZ_MTL; S = &g_S_mtl[id][0]; }
  else if (id < MTL + MTL_D)  { int r = id - MTL;  mask = g_mtlmask[r]; nnz = NNZ_DEN; S = &g_S_dense[r][0]; }
  else                        { int r = id - MTL - MTL_D; mask = g_ctxmask[r]; nnz = NNZ_CTX; S = &g_S_ctx[r][0]; }
  float sc[NSTEP];
  double R = 0.0;
  double add = (double)0.01f * (double)nnz;
  for (int t = 0; t < NSTEP; t++) {
    if ((mask >> t) & 1ull) R += add;
    float rowf = (float)R;
    float s = (rowf > 10.0f) ? (10.0f / rowf) : 1.0f;
    sc[t] = s;
    R *= (double)s;
  }
  float prod = 1.0f;
  for (int t = NSTEP - 1; t >= 0; t--) { prod *= sc[t]; S[t] = prod; }
}

// final single-shot w write: w_ij = 0.01 * sum_{t in post_i & pre_j} S_i(t)
__global__ void k_write_w(float* __restrict__ out, int which) {
  const unsigned long long* post; const unsigned long long* pre; const float* S; int ncols;
  if (which == 0)      { post = g_mtlmask; pre = g_mtlmask; S = &g_S_mtl[0][0];   ncols = MTL; }
  else if (which == 1) { post = g_mtlmask; pre = g_mtlmask; S = &g_S_dense[0][0]; ncols = MTL_D; }
  else                 { post = g_ctxmask; pre = g_ctxmask; S = &g_S_ctx[0][0];   ncols = CTX; }
  int i = blockIdx.y;
  int j = blockIdx.x * blockDim.x + threadIdx.x;
  unsigned long long m = __ldg(&post[i]) & __ldg(&pre[j]);
  float sum = 0.0f;
  while (m) {
    int t = __ffsll((long long)m) - 1;
    sum += __ldg(&S[i * NSTEP + t]);
    m &= m - 1;
  }
  out[(long long)i * ncols + j] = 0.01f * sum;
}

// ------------------------- launch -------------------------
extern "C" void kernel_launch(void* const* d_in, const int* in_sizes, int n_in,
                              void* d_out, int out_size) {
  const float* input = (const float*)d_in[0];     // [50, 2048]
  const float* Wds   = (const float*)d_in[1];     // [1024, 2048]
  const float* Wcm   = (const float*)d_in[2];     // [4096, 4096]
  float* out = (float*)d_out;

  k_zero<<<4, 1024>>>();
  k_sen<<<NSTEP, 1024>>>(input);
  k_dense_mv<<<MTL_D, 256>>>(Wds);
  k_mtl_act<<<NSTEP, 1024>>>();
  k_ctx_mv<<<CTX, 512>>>(Wcm);
  k_ctx_act<<<NSTEP, 1024>>>(out + OFF_CTXV);
  k_scales<<<(MTL + MTL_D + CTX + 255) / 256, 256>>>();
  k_write_w<<<dim3(MTL / 256, MTL), 256>>>(out + OFF_WMTL, 0);
  k_write_w<<<dim3(MTL_D / 256, MTL_D), 256>>>(out + OFF_WDENSE, 1);
  k_write_w<<<dim3(CTX / 256, CTX), 256>>>(out + OFF_WCTX, 2);
}

// round 4
// speedup vs baseline: 2.3542x; 2.3542x over previous
#include <cuda_runtime.h>
#include <cstdint>

// =====================================================================
// SESNetwork closed-form rewrite, round 4.
//   w_ij = lambda * sum_{t : post_i(t) & pre_j(t)} S_i(t),
//   S_i(t) = prod_{s>=t} scale_i(s)   (scale from row-sum recurrence).
// Activations independent of plastic weights -> parallel over t,
// each output matrix written exactly once.
// R4 change: top-k via in-smem bitonic sort of u64 keys (was O(n^2)
// rank counting), fp32 matvec accumulation (was fp64).
// =====================================================================

#define TF_PARTITIONABLE 1

#define SEN    2048
#define MTL_D  1024
#define MTL_S  3072
#define MTL    4096
#define CTX    4096
#define NSTEP  50

#define K_SEN   102
#define K_DEN   51
#define K_SPA   38
#define NNZ_MTL 203
#define NNZ_DEN 51
#define NNZ_CTX 204

#define OFF_WMTL   0LL
#define OFF_WDENSE 16777216LL
#define OFF_WCTX   17825792LL
#define OFF_CTXV   34603008LL

// ------------------------- scratch (static device) -------------------------
__device__ unsigned long long g_mtlmask[MTL];
__device__ unsigned long long g_ctxmask[CTX];
__device__ unsigned short     g_sen_idx[NSTEP][128];   // 102 used
__device__ unsigned short     g_mtl_idx[NSTEP][256];   // 203 used
__device__ float              g_hat_dense[NSTEP][MTL_D];
__device__ float              g_hat_ctx[NSTEP][CTX];
__device__ float              g_S_mtl[MTL][NSTEP];
__device__ float              g_S_dense[MTL_D][NSTEP];
__device__ float              g_S_ctx[CTX][NSTEP];

// ------------------------- threefry2x32 -------------------------
__device__ __forceinline__ uint2 tf2x32(uint32_t k0, uint32_t k1,
                                        uint32_t x0, uint32_t x1) {
  uint32_t k2 = k0 ^ k1 ^ 0x1BD11BDAu;
#define TFR(r) { x0 += x1; x1 = (x1 << (r)) | (x1 >> (32 - (r))); x1 ^= x0; }
  x0 += k0; x1 += k1;
  TFR(13) TFR(15) TFR(26) TFR(6)
  x0 += k1; x1 += k2 + 1u;
  TFR(17) TFR(29) TFR(16) TFR(24)
  x0 += k2; x1 += k0 + 2u;
  TFR(13) TFR(15) TFR(26) TFR(6)
  x0 += k0; x1 += k1 + 3u;
  TFR(17) TFR(29) TFR(16) TFR(24)
  x0 += k1; x1 += k2 + 4u;
  TFR(13) TFR(15) TFR(26) TFR(6)
  x0 += k2; x1 += k0 + 5u;
#undef TFR
  return make_uint2(x0, x1);
}

__device__ __forceinline__ uint2 fold_key(int t) {
  return tf2x32(0u, 42u, 0u, (uint32_t)t);
}

__device__ __forceinline__ uint2 skey(uint2 f, int which) {
#if TF_PARTITIONABLE
  return tf2x32(f.x, f.y, 0u, (uint32_t)which);
#else
  uint32_t r[2];
  for (int h = 0; h < 2; h++) {
    int idx = 2 * which + h;
    if (idx < 5) { uint2 o = tf2x32(f.x, f.y, (uint32_t)idx, (uint32_t)(idx + 5)); r[h] = o.x; }
    else         { uint2 o = tf2x32(f.x, f.y, (uint32_t)(idx - 5), (uint32_t)idx); r[h] = o.y; }
  }
  return make_uint2(r[0], r[1]);
#endif
}

// XLA f32 ErfInv (Giles polynomial)
__device__ __forceinline__ float erfinv_xla(float x) {
  float xx = x * x;
  float w = -log1pf(-xx);
  float p;
  if (w < 5.0f) {
    w -= 2.5f;
    p = 2.81022636e-08f;
    p = fmaf(p, w, 3.43273939e-07f);
    p = fmaf(p, w, -3.5233877e-06f);
    p = fmaf(p, w, -4.39150654e-06f);
    p = fmaf(p, w, 0.00021858087f);
    p = fmaf(p, w, -0.00125372503f);
    p = fmaf(p, w, -0.00417768164f);
    p = fmaf(p, w, 0.246640727f);
    p = fmaf(p, w, 1.50140941f);
  } else {
    w = sqrtf(w) - 3.0f;
    p = -0.000200214257f;
    p = fmaf(p, w, 0.000100950558f);
    p = fmaf(p, w, 0.00134934322f);
    p = fmaf(p, w, -0.00367342844f);
    p = fmaf(p, w, 0.00573950773f);
    p = fmaf(p, w, -0.0076224613f);
    p = fmaf(p, w, 0.00943887047f);
    p = fmaf(p, w, 1.00167406f);
    p = fmaf(p, w, 2.83297682f);
  }
  return p * x;
}

__device__ __forceinline__ float jnormal(uint2 key, uint32_t j, uint32_t N) {
  uint32_t bits;
#if TF_PARTITIONABLE
  uint2 o = tf2x32(key.x, key.y, 0u, j);
  bits = o.x ^ o.y;
#else
  uint32_t h = N / 2;
  if (j < h) { uint2 o = tf2x32(key.x, key.y, j, j + h); bits = o.x; }
  else       { uint2 o = tf2x32(key.x, key.y, j - h, j); bits = o.y; }
#endif
  float f = __uint_as_float((bits >> 9) | 0x3f800000u) - 1.0f;
  const float LO = -0.99999994039535522461f;
  float u = fmaxf(LO, fmaf(f, 2.0f, LO));
  return 1.4142135381698608f * erfinv_xla(u);
}

// composite key: descending value, ascending index on ties; >0 for finite v
__device__ __forceinline__ unsigned long long ckey(float v, uint32_t idx) {
  uint32_t u = __float_as_uint(v);
  u = (u & 0x80000000u) ? ~u : (u | 0x80000000u);
  return ((unsigned long long)u << 32) | (uint32_t)(~idx);
}

__device__ void block_maxmin(float x, float n, float* s_red, float& omx, float& omn) {
  int lane = threadIdx.x & 31, w = threadIdx.x >> 5;
  int nw = (int)(blockDim.x >> 5);
  for (int o = 16; o; o >>= 1) {
    x = fmaxf(x, __shfl_xor_sync(0xffffffffu, x, o));
    n = fminf(n, __shfl_xor_sync(0xffffffffu, n, o));
  }
  if (lane == 0) { s_red[w] = x; s_red[32 + w] = n; }
  __syncthreads();
  if (w == 0) {
    x = (lane < nw) ? s_red[lane]      : -3.402823466e38f;
    n = (lane < nw) ? s_red[32 + lane] :  3.402823466e38f;
    for (int o = 16; o; o >>= 1) {
      x = fmaxf(x, __shfl_xor_sync(0xffffffffu, x, o));
      n = fminf(n, __shfl_xor_sync(0xffffffffu, n, o));
    }
    if (lane == 0) { s_red[0] = x; s_red[32] = n; }
  }
  __syncthreads();
  omx = s_red[0]; omn = s_red[32];
  __syncthreads();
}

// Descending bitonic sort of NARR independent arrays of length 2^NLOG2,
// stacked contiguously in smem. Pairs within a pass are disjoint.
template<int NLOG2, int NARR>
__device__ void bitonic_desc(unsigned long long* sk) {
  const int N = 1 << NLOG2;
  const int HALF = N >> 1;
  const int TOTAL = NARR * HALF;
  int tid = threadIdx.x, nth = (int)blockDim.x;
  for (int ksz = 2; ksz <= N; ksz <<= 1) {
    for (int j = ksz >> 1; j > 0; j >>= 1) {
      __syncthreads();
      for (int p = tid; p < TOTAL; p += nth) {
        int a = p >> (NLOG2 - 1);
        int r = p & (HALF - 1);
        int i1 = ((r & ~(j - 1)) << 1) | (r & (j - 1));
        int g = a * N + i1;
        unsigned long long x = sk[g], y = sk[g + j];
        bool desc = ((i1 & ksz) == 0);
        if ((x < y) == desc) { sk[g] = y; sk[g + j] = x; }
      }
    }
  }
  __syncthreads();
}

// ------------------------- kernels -------------------------

__global__ void k_zero() {
  int i = blockIdx.x * blockDim.x + threadIdx.x;
  if (i < MTL) { g_mtlmask[i] = 0ull; g_ctxmask[i] = 0ull; }
}

// sen activation: one block per step, sort 2048 keys
__global__ void k_sen(const float* __restrict__ input) {
  __shared__ unsigned long long sk[SEN];       // 16 KB
  __shared__ float s_red[64];
  int t = blockIdx.x, tid = threadIdx.x;       // 1024 threads
  uint2 f = fold_key(t);
  uint2 kn = skey(f, 0);
  float v0 = input[t * SEN + tid];
  float v1 = input[t * SEN + tid + 1024];
  float mx, mn;
  block_maxmin(fmaxf(v0, v1), fminf(v0, v1), s_red, mx, mn);
  float amp = ((1e-10f + mx) - mn) / 100.0f;
  sk[tid]        = ckey(v0 + amp * jnormal(kn, (uint32_t)tid, SEN), (uint32_t)tid);
  sk[tid + 1024] = ckey(v1 + amp * jnormal(kn, (uint32_t)(tid + 1024), SEN), (uint32_t)(tid + 1024));
  bitonic_desc<11, 1>(sk);
  if (tid < K_SEN) g_sen_idx[t][tid] = (unsigned short)(~(unsigned)sk[tid]);
}

// dense matvec: one block per dense row; gather from smem row for all t
__global__ void k_dense_mv(const float* __restrict__ Wds) {
  __shared__ float row[SEN];                   // 8 KB
  __shared__ unsigned short idx[NSTEP * 128];  // 12.8 KB
  int r = blockIdx.x, tid = threadIdx.x;       // 256 threads
  for (int i = tid; i < SEN; i += 256) row[i] = Wds[(long long)r * SEN + i];
  const unsigned short* src = &g_sen_idx[0][0];
  for (int i = tid; i < NSTEP * 128; i += 256) idx[i] = src[i];
  __syncthreads();
  int w = tid >> 5, l = tid & 31;              // 8 warps
  for (int t = w; t < NSTEP; t += 8) {
    float acc = 0.0f;
    for (int m = l; m < K_SEN; m += 32) acc += row[idx[t * 128 + m]];
    for (int o = 16; o; o >>= 1) acc += __shfl_xor_sync(0xffffffffu, acc, o);
    if (l == 0) g_hat_dense[t][r] = acc;
  }
}

// mtl activation: 5 sorts of 1024 (dense + 4 padded sparse subregions)
__global__ void k_mtl_act() {
  __shared__ unsigned long long ks[5 * 1024];  // 40 KB
  __shared__ float s_red[64];
  int t = blockIdx.x, tid = threadIdx.x;       // 1024 threads
  uint2 f = fold_key(t);
  uint2 K1 = skey(f, 1), K2 = skey(f, 2), K3 = skey(f, 3);

  float vd = g_hat_dense[t][tid];
  float vs[3];
#pragma unroll
  for (int e = 0; e < 3; e++) vs[e] = jnormal(K2, (uint32_t)(tid + e * 1024), MTL_S);

  float mx, mn;
  block_maxmin(vd, vd, s_red, mx, mn);
  float amp_d = ((1e-10f + mx) - mn) / 100.0f;
  block_maxmin(fmaxf(vs[0], fmaxf(vs[1], vs[2])),
               fminf(vs[0], fminf(vs[1], vs[2])), s_red, mx, mn);
  float amp_s = ((1e-10f + mx) - mn) / 100.0f;

  ks[tid] = ckey(vd + amp_d * jnormal(K1, (uint32_t)tid, MTL_D), (uint32_t)tid);
#pragma unroll
  for (int e = 0; e < 3; e++) {
    int j = tid + e * 1024;                 // 0..3071
    int pos = 1024 + (j / 768) * 1024 + (j % 768);
    ks[pos] = ckey(vs[e] + amp_s * jnormal(K3, (uint32_t)j, MTL_S),
                   (uint32_t)(MTL_D + j));  // store global mtl index
  }
  { // pad each sparse array positions 768..1023 with key 0 (< any finite key)
    int s = tid >> 8, q = tid & 255;
    ks[1024 + s * 1024 + 768 + q] = 0ull;
  }
  bitonic_desc<10, 5>(ks);
  if (tid < NNZ_MTL) {
    unsigned long long key;
    if (tid < K_DEN) key = ks[tid];
    else {
      int s = (tid - K_DEN) / K_SPA, q = (tid - K_DEN) % K_SPA;
      key = ks[(1 + s) * 1024 + q];
    }
    int idx = (int)(~(unsigned)key);
    g_mtl_idx[t][tid] = (unsigned short)idx;
    atomicOr(&g_mtlmask[idx], 1ull << t);
  }
}

// ctx matvec: one block per ctx row; gather from smem row for all t
__global__ void k_ctx_mv(const float* __restrict__ Wcm) {
  __shared__ float row[MTL];                   // 16 KB
  __shared__ unsigned short idx[NSTEP * 256];  // 25.6 KB
  int r = blockIdx.x, tid = threadIdx.x;       // 512 threads
  for (int i = tid; i < MTL; i += 512) row[i] = Wcm[(long long)r * MTL + i];
  const unsigned short* src = &g_mtl_idx[0][0];
  for (int i = tid; i < NSTEP * 256; i += 512) idx[i] = src[i];
  __syncthreads();
  int w = tid >> 5, l = tid & 31;              // 16 warps
  for (int t = w; t < NSTEP; t += 16) {
    float acc = 0.0f;
    for (int m = l; m < NNZ_MTL; m += 32) acc += row[idx[t * 256 + m]];
    for (int o = 16; o; o >>= 1) acc += __shfl_xor_sync(0xffffffffu, acc, o);
    if (l == 0) g_hat_ctx[t][r] = acc;
  }
}

// ctx activation: 4 sorts of 1024; emits final ctx vector at t==49
__global__ void k_ctx_act(float* __restrict__ out_ctx) {
  __shared__ unsigned long long kc[CTX];       // 32 KB
  __shared__ float s_red[64];
  int t = blockIdx.x, tid = threadIdx.x;       // 1024 threads
  uint2 f = fold_key(t);
  uint2 K4 = skey(f, 4);
  float v[4];
  float lmx = -3.402823466e38f, lmn = 3.402823466e38f;
#pragma unroll
  for (int e = 0; e < 4; e++) {
    v[e] = g_hat_ctx[t][tid + e * 1024];
    lmx = fmaxf(lmx, v[e]); lmn = fminf(lmn, v[e]);
  }
  float mx, mn;
  block_maxmin(lmx, lmn, s_red, mx, mn);
  float amp = ((1e-10f + mx) - mn) / 100.0f;
  if (t == NSTEP - 1) {
#pragma unroll
    for (int e = 0; e < 4; e++) out_ctx[tid + e * 1024] = 0.0f;
  }
#pragma unroll
  for (int e = 0; e < 4; e++) {
    int j = tid + e * 1024;
    kc[j] = ckey(v[e] + amp * jnormal(K4, (uint32_t)j, CTX), (uint32_t)j);
  }
  bitonic_desc<10, 4>(kc);
  if (tid < 4 * K_DEN) {
    int a = tid / K_DEN, q = tid % K_DEN;
    int j = (int)(~(unsigned)kc[a * 1024 + q]);
    atomicOr(&g_ctxmask[j], 1ull << t);
    if (t == NSTEP - 1) out_ctx[j] = 1.0f;   // ordered after zeros by the sort's barriers
  }
}

// per-row homeostasis scale suffix products
__global__ void k_scales() {
  int id = blockIdx.x * blockDim.x + threadIdx.x;
  if (id >= MTL + MTL_D + CTX) return;
  unsigned long long mask; int nnz; float* S;
  if (id < MTL)              { mask = g_mtlmask[id];            nnz = NNZ_MTL; S = &g_S_mtl[id][0]; }
  else if (id < MTL + MTL_D) { int r = id - MTL; mask = g_mtlmask[r]; nnz = NNZ_DEN; S = &g_S_dense[r][0]; }
  else                       { int r = id - MTL - MTL_D; mask = g_ctxmask[r]; nnz = NNZ_CTX; S = &g_S_ctx[r][0]; }
  float sc[NSTEP];
  double R = 0.0;
  double add = (double)0.01f * (double)nnz;
  for (int t = 0; t < NSTEP; t++) {
    if ((mask >> t) & 1ull) R += add;
    float rowf = (float)R;
    float s = (rowf > 10.0f) ? (10.0f / rowf) : 1.0f;
    sc[t] = s;
    R *= (double)s;
  }
  float prod = 1.0f;
  for (int t = NSTEP - 1; t >= 0; t--) { prod *= sc[t]; S[t] = prod; }
}

// single-shot w write: w_ij = 0.01 * sum_{t in post_i & pre_j} S_i(t)
__global__ void k_write_w(float* __restrict__ out, int which) {
  const unsigned long long* post; const unsigned long long* pre; const float* S; int ncols;
  if (which == 0)      { post = g_mtlmask; pre = g_mtlmask; S = &g_S_mtl[0][0];   ncols = MTL; }
  else if (which == 1) { post = g_mtlmask; pre = g_mtlmask; S = &g_S_dense[0][0]; ncols = MTL_D; }
  else                 { post = g_ctxmask; pre = g_ctxmask; S = &g_S_ctx[0][0];   ncols = CTX; }
  int i = blockIdx.y;
  int j = blockIdx.x * blockDim.x + threadIdx.x;
  unsigned long long m = __ldg(&post[i]) & __ldg(&pre[j]);
  float sum = 0.0f;
  while (m) {
    int t = __ffsll((long long)m) - 1;
    sum += __ldg(&S[i * NSTEP + t]);
    m &= m - 1;
  }
  out[(long long)i * ncols + j] = 0.01f * sum;
}

// ------------------------- launch -------------------------
extern "C" void kernel_launch(void* const* d_in, const int* in_sizes, int n_in,
                              void* d_out, int out_size) {
  const float* input = (const float*)d_in[0];     // [50, 2048]
  const float* Wds   = (const float*)d_in[1];     // [1024, 2048]
  const float* Wcm   = (const float*)d_in[2];     // [4096, 4096]
  float* out = (float*)d_out;

  k_zero<<<4, 1024>>>();
  k_sen<<<NSTEP, 1024>>>(input);
  k_dense_mv<<<MTL_D, 256>>>(Wds);
  k_mtl_act<<<NSTEP, 1024>>>();
  k_ctx_mv<<<CTX, 512>>>(Wcm);
  k_ctx_act<<<NSTEP, 1024>>>(out + OFF_CTXV);
  k_scales<<<(MTL + MTL_D + CTX + 255) / 256, 256>>>();
  k_write_w<<<dim3(MTL / 256, MTL), 256>>>(out + OFF_WMTL, 0);
  k_write_w<<<dim3(MTL_D / 256, MTL_D), 256>>>(out + OFF_WDENSE, 1);
  k_write_w<<<dim3(CTX / 256, CTX), 256>>>(out + OFF_WCTX, 2);
}

// round 5
// speedup vs baseline: 2.6214x; 1.1135x over previous
#include <cuda_runtime.h>
#include <cstdint>

// =====================================================================
// SESNetwork closed-form rewrite, round 5.
//   w_ij = lambda * sum_{t : post_i(t) & pre_j(t)} S_i(t),
//   S_i(t) = prod_{s>=t} scale_i(s).
// R5: sorts decomposed to one block per (t, subregion) @ 256 threads
// (was one 1024-thread block per step); amp reductions hoisted into
// tiny grid-50 kernels; float4 matvec loads; smem-cached S row in
// the weight-write kernels.
// =====================================================================

#define TF_PARTITIONABLE 1

#define SEN    2048
#define MTL_D  1024
#define MTL_S  3072
#define MTL    4096
#define CTX    4096
#define NSTEP  50

#define K_SEN   102
#define K_DEN   51
#define K_SPA   38
#define NNZ_MTL 203
#define NNZ_DEN 51
#define NNZ_CTX 204

#define OFF_WMTL   0LL
#define OFF_WDENSE 16777216LL
#define OFF_WCTX   17825792LL
#define OFF_CTXV   34603008LL

// ------------------------- scratch (static device) -------------------------
__device__ unsigned long long g_mtlmask[MTL];
__device__ unsigned long long g_ctxmask[CTX];
__device__ unsigned short     g_sen_idx[NSTEP][128];   // 102 used
__device__ unsigned short     g_mtl_idx[NSTEP][256];   // 203 used
__device__ float              g_hat_dense[NSTEP][MTL_D];
__device__ float              g_hat_sparse[NSTEP][MTL_S];
__device__ float              g_hat_ctx[NSTEP][CTX];
__device__ float              g_amp_d[NSTEP];
__device__ float              g_amp_s[NSTEP];
__device__ float              g_amp_c[NSTEP];
__device__ float              g_S_mtl[MTL][NSTEP];
__device__ float              g_S_dense[MTL_D][NSTEP];
__device__ float              g_S_ctx[CTX][NSTEP];

// ------------------------- threefry2x32 -------------------------
__device__ __forceinline__ uint2 tf2x32(uint32_t k0, uint32_t k1,
                                        uint32_t x0, uint32_t x1) {
  uint32_t k2 = k0 ^ k1 ^ 0x1BD11BDAu;
#define TFR(r) { x0 += x1; x1 = (x1 << (r)) | (x1 >> (32 - (r))); x1 ^= x0; }
  x0 += k0; x1 += k1;
  TFR(13) TFR(15) TFR(26) TFR(6)
  x0 += k1; x1 += k2 + 1u;
  TFR(17) TFR(29) TFR(16) TFR(24)
  x0 += k2; x1 += k0 + 2u;
  TFR(13) TFR(15) TFR(26) TFR(6)
  x0 += k0; x1 += k1 + 3u;
  TFR(17) TFR(29) TFR(16) TFR(24)
  x0 += k1; x1 += k2 + 4u;
  TFR(13) TFR(15) TFR(26) TFR(6)
  x0 += k2; x1 += k0 + 5u;
#undef TFR
  return make_uint2(x0, x1);
}

__device__ __forceinline__ uint2 fold_key(int t) {
  return tf2x32(0u, 42u, 0u, (uint32_t)t);
}

__device__ __forceinline__ uint2 skey(uint2 f, int which) {
#if TF_PARTITIONABLE
  return tf2x32(f.x, f.y, 0u, (uint32_t)which);
#else
  uint32_t r[2];
  for (int h = 0; h < 2; h++) {
    int idx = 2 * which + h;
    if (idx < 5) { uint2 o = tf2x32(f.x, f.y, (uint32_t)idx, (uint32_t)(idx + 5)); r[h] = o.x; }
    else         { uint2 o = tf2x32(f.x, f.y, (uint32_t)(idx - 5), (uint32_t)idx); r[h] = o.y; }
  }
  return make_uint2(r[0], r[1]);
#endif
}

// XLA f32 ErfInv (Giles polynomial)
__device__ __forceinline__ float erfinv_xla(float x) {
  float xx = x * x;
  float w = -log1pf(-xx);
  float p;
  if (w < 5.0f) {
    w -= 2.5f;
    p = 2.81022636e-08f;
    p = fmaf(p, w, 3.43273939e-07f);
    p = fmaf(p, w, -3.5233877e-06f);
    p = fmaf(p, w, -4.39150654e-06f);
    p = fmaf(p, w, 0.00021858087f);
    p = fmaf(p, w, -0.00125372503f);
    p = fmaf(p, w, -0.00417768164f);
    p = fmaf(p, w, 0.246640727f);
    p = fmaf(p, w, 1.50140941f);
  } else {
    w = sqrtf(w) - 3.0f;
    p = -0.000200214257f;
    p = fmaf(p, w, 0.000100950558f);
    p = fmaf(p, w, 0.00134934322f);
    p = fmaf(p, w, -0.00367342844f);
    p = fmaf(p, w, 0.00573950773f);
    p = fmaf(p, w, -0.0076224613f);
    p = fmaf(p, w, 0.00943887047f);
    p = fmaf(p, w, 1.00167406f);
    p = fmaf(p, w, 2.83297682f);
  }
  return p * x;
}

__device__ __forceinline__ float jnormal(uint2 key, uint32_t j, uint32_t N) {
  uint32_t bits;
#if TF_PARTITIONABLE
  uint2 o = tf2x32(key.x, key.y, 0u, j);
  bits = o.x ^ o.y;
#else
  uint32_t h = N / 2;
  if (j < h) { uint2 o = tf2x32(key.x, key.y, j, j + h); bits = o.x; }
  else       { uint2 o = tf2x32(key.x, key.y, j - h, j); bits = o.y; }
#endif
  float f = __uint_as_float((bits >> 9) | 0x3f800000u) - 1.0f;
  const float LO = -0.99999994039535522461f;
  float u = fmaxf(LO, fmaf(f, 2.0f, LO));
  return 1.4142135381698608f * erfinv_xla(u);
}

// composite key: descending value, ascending index on ties; >0 for finite v
__device__ __forceinline__ unsigned long long ckey(float v, uint32_t idx) {
  uint32_t u = __float_as_uint(v);
  u = (u & 0x80000000u) ? ~u : (u | 0x80000000u);
  return ((unsigned long long)u << 32) | (uint32_t)(~idx);
}

__device__ void block_maxmin(float x, float n, float* s_red, float& omx, float& omn) {
  int lane = threadIdx.x & 31, w = threadIdx.x >> 5;
  int nw = (int)(blockDim.x >> 5);
  for (int o = 16; o; o >>= 1) {
    x = fmaxf(x, __shfl_xor_sync(0xffffffffu, x, o));
    n = fminf(n, __shfl_xor_sync(0xffffffffu, n, o));
  }
  if (lane == 0) { s_red[w] = x; s_red[32 + w] = n; }
  __syncthreads();
  if (w == 0) {
    x = (lane < nw) ? s_red[lane]      : -3.402823466e38f;
    n = (lane < nw) ? s_red[32 + lane] :  3.402823466e38f;
    for (int o = 16; o; o >>= 1) {
      x = fmaxf(x, __shfl_xor_sync(0xffffffffu, x, o));
      n = fminf(n, __shfl_xor_sync(0xffffffffu, n, o));
    }
    if (lane == 0) { s_red[0] = x; s_red[32] = n; }
  }
  __syncthreads();
  omx = s_red[0]; omn = s_red[32];
  __syncthreads();
}

// Descending bitonic sort of one array of length 2^NLOG2 in smem.
template<int NLOG2>
__device__ void bitonic_desc1(unsigned long long* sk) {
  const int N = 1 << NLOG2;
  const int HALF = N >> 1;
  int tid = threadIdx.x, nth = (int)blockDim.x;
  for (int ksz = 2; ksz <= N; ksz <<= 1) {
    for (int j = ksz >> 1; j > 0; j >>= 1) {
      __syncthreads();
      for (int r = tid; r < HALF; r += nth) {
        int i1 = ((r & ~(j - 1)) << 1) | (r & (j - 1));
        unsigned long long x = sk[i1], y = sk[i1 + j];
        bool desc = ((i1 & ksz) == 0);
        if ((x < y) == desc) { sk[i1] = y; sk[i1 + j] = x; }
      }
    }
  }
  __syncthreads();
}

// ------------------------- kernels -------------------------

__global__ void k_zero(float* __restrict__ out_ctx) {
  int i = blockIdx.x * blockDim.x + threadIdx.x;
  if (i < MTL) { g_mtlmask[i] = 0ull; g_ctxmask[i] = 0ull; }
  if (i < CTX) out_ctx[i] = 0.0f;
}

// sen activation: one block per step (512 thr), sort 2048 keys
__global__ void k_sen(const float* __restrict__ input) {
  __shared__ unsigned long long sk[SEN];       // 16 KB
  __shared__ float s_red[64];
  int t = blockIdx.x, tid = threadIdx.x;       // 512 threads
  uint2 f = fold_key(t);
  uint2 kn = skey(f, 0);
  float v[4];
  float lmx = -3.402823466e38f, lmn = 3.402823466e38f;
#pragma unroll
  for (int e = 0; e < 4; e++) {
    v[e] = input[t * SEN + tid + e * 512];
    lmx = fmaxf(lmx, v[e]); lmn = fminf(lmn, v[e]);
  }
  float mx, mn;
  block_maxmin(lmx, lmn, s_red, mx, mn);
  float amp = ((1e-10f + mx) - mn) / 100.0f;
#pragma unroll
  for (int e = 0; e < 4; e++) {
    int j = tid + e * 512;
    sk[j] = ckey(v[e] + amp * jnormal(kn, (uint32_t)j, SEN), (uint32_t)j);
  }
  bitonic_desc1<11>(sk);
  if (tid < K_SEN) g_sen_idx[t][tid] = (unsigned short)(~(unsigned)sk[tid]);
}

// dense matvec: one block per dense row; gather from smem row for all t
__global__ void k_dense_mv(const float* __restrict__ Wds) {
  __shared__ float row[SEN];                   // 8 KB
  __shared__ unsigned short idx[NSTEP * 128];  // 12.8 KB
  int r = blockIdx.x, tid = threadIdx.x;       // 256 threads
  const float4* src4 = (const float4*)(Wds + (long long)r * SEN);
#pragma unroll
  for (int i = tid; i < SEN / 4; i += 256) ((float4*)row)[i] = src4[i];
  const uint32_t* isrc = (const uint32_t*)&g_sen_idx[0][0];
  for (int i = tid; i < NSTEP * 64; i += 256) ((uint32_t*)idx)[i] = isrc[i];
  __syncthreads();
  int w = tid >> 5, l = tid & 31;              // 8 warps
  for (int t = w; t < NSTEP; t += 8) {
    float acc = 0.0f;
    for (int m = l; m < K_SEN; m += 32) acc += row[idx[t * 128 + m]];
    for (int o = 16; o; o >>= 1) acc += __shfl_xor_sync(0xffffffffu, acc, o);
    if (l == 0) g_hat_dense[t][r] = acc;
  }
}

// amp reductions + sparse hat generation: one block per step
__global__ void k_amp_mtl() {
  __shared__ float s_red[64];
  int t = blockIdx.x, tid = threadIdx.x;       // 1024 threads
  uint2 f = fold_key(t);
  uint2 K2 = skey(f, 2);
  float vd = g_hat_dense[t][tid];
  float mx, mn;
  block_maxmin(vd, vd, s_red, mx, mn);
  if (tid == 0) g_amp_d[t] = ((1e-10f + mx) - mn) / 100.0f;
  float vs[3];
#pragma unroll
  for (int e = 0; e < 3; e++) {
    int j = tid + e * 1024;
    vs[e] = jnormal(K2, (uint32_t)j, MTL_S);
    g_hat_sparse[t][j] = vs[e];
  }
  block_maxmin(fmaxf(vs[0], fmaxf(vs[1], vs[2])),
               fminf(vs[0], fminf(vs[1], vs[2])), s_red, mx, mn);
  if (tid == 0) g_amp_s[t] = ((1e-10f + mx) - mn) / 100.0f;
}

// mtl sorts: one block per (subregion a in 0..4, step t); 256 threads
__global__ void k_mtl_sort() {
  __shared__ unsigned long long sk[1024];      // 8 KB
  int a = blockIdx.x, t = blockIdx.y, tid = threadIdx.x;
  uint2 f = fold_key(t);
  if (a == 0) {
    uint2 K1 = skey(f, 1);
    float amp = g_amp_d[t];
#pragma unroll
    for (int e = 0; e < 4; e++) {
      int q = tid + e * 256;
      float v = g_hat_dense[t][q] + amp * jnormal(K1, (uint32_t)q, MTL_D);
      sk[q] = ckey(v, (uint32_t)q);
    }
    bitonic_desc1<10>(sk);
    if (tid < K_DEN) {
      int idx = (int)(~(unsigned)sk[tid]);
      g_mtl_idx[t][tid] = (unsigned short)idx;
      atomicOr(&g_mtlmask[idx], 1ull << t);
    }
  } else {
    int s = a - 1;
    uint2 K3 = skey(f, 3);
    float amp = g_amp_s[t];
#pragma unroll
    for (int e = 0; e < 4; e++) {
      int q = tid + e * 256;
      if (q < 768) {
        int j = s * 768 + q;
        float v = g_hat_sparse[t][j] + amp * jnormal(K3, (uint32_t)j, MTL_S);
        sk[q] = ckey(v, (uint32_t)(MTL_D + j));
      } else {
        sk[q] = 0ull;   // below any finite key
      }
    }
    bitonic_desc1<10>(sk);
    if (tid < K_SPA) {
      int idx = (int)(~(unsigned)sk[tid]);
      g_mtl_idx[t][K_DEN + s * K_SPA + tid] = (unsigned short)idx;
      atomicOr(&g_mtlmask[idx], 1ull << t);
    }
  }
}

// ctx matvec: one block per ctx row; gather from smem row for all t
__global__ void k_ctx_mv(const float* __restrict__ Wcm) {
  __shared__ float row[MTL];                   // 16 KB
  __shared__ unsigned short idx[NSTEP * 256];  // 25.6 KB
  int r = blockIdx.x, tid = threadIdx.x;       // 512 threads
  const float4* src4 = (const float4*)(Wcm + (long long)r * MTL);
#pragma unroll
  for (int i = tid; i < MTL / 4; i += 512) ((float4*)row)[i] = src4[i];
  const uint32_t* isrc = (const uint32_t*)&g_mtl_idx[0][0];
  for (int i = tid; i < NSTEP * 128; i += 512) ((uint32_t*)idx)[i] = isrc[i];
  __syncthreads();
  int w = tid >> 5, l = tid & 31;              // 16 warps
  for (int t = w; t < NSTEP; t += 16) {
    float acc = 0.0f;
    for (int m = l; m < NNZ_MTL; m += 32) acc += row[idx[t * 256 + m]];
    for (int o = 16; o; o >>= 1) acc += __shfl_xor_sync(0xffffffffu, acc, o);
    if (l == 0) g_hat_ctx[t][r] = acc;
  }
}

// ctx amp: one block per step
__global__ void k_ctx_amp() {
  __shared__ float s_red[64];
  int t = blockIdx.x, tid = threadIdx.x;       // 1024 threads
  float lmx = -3.402823466e38f, lmn = 3.402823466e38f;
#pragma unroll
  for (int e = 0; e < 4; e++) {
    float v = g_hat_ctx[t][tid + e * 1024];
    lmx = fmaxf(lmx, v); lmn = fminf(lmn, v);
  }
  float mx, mn;
  block_maxmin(lmx, lmn, s_red, mx, mn);
  if (tid == 0) g_amp_c[t] = ((1e-10f + mx) - mn) / 100.0f;
}

// ctx sorts: one block per (subregion a in 0..3, step t); 256 threads
__global__ void k_ctx_sort(float* __restrict__ out_ctx) {
  __shared__ unsigned long long sk[1024];      // 8 KB
  int a = blockIdx.x, t = blockIdx.y, tid = threadIdx.x;
  uint2 f = fold_key(t);
  uint2 K4 = skey(f, 4);
  float amp = g_amp_c[t];
#pragma unroll
  for (int e = 0; e < 4; e++) {
    int q = tid + e * 256;
    int j = a * 1024 + q;
    float v = g_hat_ctx[t][j] + amp * jnormal(K4, (uint32_t)j, CTX);
    sk[q] = ckey(v, (uint32_t)j);
  }
  bitonic_desc1<10>(sk);
  if (tid < K_DEN) {
    int j = (int)(~(unsigned)sk[tid]);
    atomicOr(&g_ctxmask[j], 1ull << t);
    if (t == NSTEP - 1) out_ctx[j] = 1.0f;  // zeros written by k_zero
  }
}

// per-row homeostasis scale suffix products
__global__ void k_scales() {
  int id = blockIdx.x * blockDim.x + threadIdx.x;
  if (id >= MTL + MTL_D + CTX) return;
  unsigned long long mask; int nnz; float* S;
  if (id < MTL)              { mask = g_mtlmask[id];            nnz = NNZ_MTL; S = &g_S_mtl[id][0]; }
  else if (id < MTL + MTL_D) { int r = id - MTL; mask = g_mtlmask[r]; nnz = NNZ_DEN; S = &g_S_dense[r][0]; }
  else                       { int r = id - MTL - MTL_D; mask = g_ctxmask[r]; nnz = NNZ_CTX; S = &g_S_ctx[r][0]; }
  float sc[NSTEP];
  double R = 0.0;
  double add = (double)0.01f * (double)nnz;
  for (int t = 0; t < NSTEP; t++) {
    if ((mask >> t) & 1ull) R += add;
    float rowf = (float)R;
    float s = (rowf > 10.0f) ? (10.0f / rowf) : 1.0f;
    sc[t] = s;
    R *= (double)s;
  }
  float prod = 1.0f;
  for (int t = NSTEP - 1; t >= 0; t--) { prod *= sc[t]; S[t] = prod; }
}

// single-shot w write: w_ij = 0.01 * sum_{t in post_i & pre_j} S_i(t)
__global__ void k_write_w(float* __restrict__ out, int which) {
  const unsigned long long* post; const unsigned long long* pre; const float* S; int ncols;
  if (which == 0)      { post = g_mtlmask; pre = g_mtlmask; S = &g_S_mtl[0][0];   ncols = MTL; }
  else if (which == 1) { post = g_mtlmask; pre = g_mtlmask; S = &g_S_dense[0][0]; ncols = MTL_D; }
  else                 { post = g_ctxmask; pre = g_ctxmask; S = &g_S_ctx[0][0];   ncols = CTX; }
  __shared__ float sS[NSTEP];
  __shared__ unsigned long long spost;
  int i = blockIdx.y;
  if (threadIdx.x < NSTEP) sS[threadIdx.x] = S[i * NSTEP + threadIdx.x];
  if (threadIdx.x == 0) spost = post[i];
  __syncthreads();
  int j = blockIdx.x * blockDim.x + threadIdx.x;
  unsigned long long m = spost & pre[j];
  float sum = 0.0f;
  while (m) {
    int t = __ffsll((long long)m) - 1;
    sum += sS[t];
    m &= m - 1;
  }
  out[(long long)i * ncols + j] = 0.01f * sum;
}

// ------------------------- launch -------------------------
extern "C" void kernel_launch(void* const* d_in, const int* in_sizes, int n_in,
                              void* d_out, int out_size) {
  const float* input = (const float*)d_in[0];     // [50, 2048]
  const float* Wds   = (const float*)d_in[1];     // [1024, 2048]
  const float* Wcm   = (const float*)d_in[2];     // [4096, 4096]
  float* out = (float*)d_out;

  k_zero<<<4, 1024>>>(out + OFF_CTXV);
  k_sen<<<NSTEP, 512>>>(input);
  k_dense_mv<<<MTL_D, 256>>>(Wds);
  k_amp_mtl<<<NSTEP, 1024>>>();
  k_mtl_sort<<<dim3(5, NSTEP), 256>>>();
  k_ctx_mv<<<CTX, 512>>>(Wcm);
  k_ctx_amp<<<NSTEP, 1024>>>();
  k_ctx_sort<<<dim3(4, NSTEP), 256>>>(out + OFF_CTXV);
  k_scales<<<(MTL + MTL_D + CTX + 255) / 256, 256>>>();
  k_write_w<<<dim3(MTL / 256, MTL), 256>>>(out + OFF_WMTL, 0);
  k_write_w<<<dim3(MTL_D / 256, MTL_D), 256>>>(out + OFF_WDENSE, 1);
  k_write_w<<<dim3(CTX / 256, CTX), 256>>>(out + OFF_WCTX, 2);
}